// round 14
// baseline (speedup 1.0000x reference)
#include <cuda_runtime.h>
#include <cuda_fp16.h>
#include <math.h>
#include <stdint.h>

#define D_    128
#define A_    16
#define HID_  128
#define KW1   272
#define MT    128
#define EMAX  1000000
#define GMAXN 25600
#define STRA  176      // A smem row stride (80 fp16 = 160B + 16 pad)
#define STRB  144      // B smem row stride (64 fp16 = 128B + 16 pad)

// -------- scratch (device globals; no allocs allowed) --------
__device__ float  g_sum[GMAXN];
__device__ double g_partd[EMAX];     // biased cross-CTA logit accumulator (zero-init)
__device__ __align__(16) __half g_w1h[KW1 * HID_];   // W1 fp16 [k][n]

#define BIAS1 1073741824.0   // 2^30
#define BIAS2 2147483648.0   // 2^31

__device__ __forceinline__ uint32_t smem_u32(const void* p) {
    uint32_t a;
    asm("{ .reg .u64 t; cvta.to.shared.u64 t, %1; cvt.u32.u64 %0, t; }" : "=r"(a) : "l"(p));
    return a;
}
__device__ __forceinline__ void ldsm_x4(uint32_t* r, uint32_t addr) {
    asm volatile("ldmatrix.sync.aligned.m8n8.x4.shared.b16 {%0,%1,%2,%3}, [%4];"
                 : "=r"(r[0]), "=r"(r[1]), "=r"(r[2]), "=r"(r[3]) : "r"(addr));
}
__device__ __forceinline__ void ldsm_x4_t(uint32_t* r, uint32_t addr) {
    asm volatile("ldmatrix.sync.aligned.m8n8.x4.trans.shared.b16 {%0,%1,%2,%3}, [%4];"
                 : "=r"(r[0]), "=r"(r[1]), "=r"(r[2]), "=r"(r[3]) : "r"(addr));
}
__device__ __forceinline__ void mma16816(float* c, const uint32_t* a, uint32_t b0, uint32_t b1) {
    asm volatile("mma.sync.aligned.m16n8k16.row.col.f32.f16.f16.f32 "
                 "{%0,%1,%2,%3}, {%4,%5,%6,%7}, {%8,%9}, {%0,%1,%2,%3};"
                 : "+f"(c[0]), "+f"(c[1]), "+f"(c[2]), "+f"(c[3])
                 : "r"(a[0]), "r"(a[1]), "r"(a[2]), "r"(a[3]), "r"(b0), "r"(b1));
}
__device__ __forceinline__ void cp16(uint32_t sdst, const void* gsrc) {
    asm volatile("cp.async.cg.shared.global [%0], [%1], 16;" :: "r"(sdst), "l"(gsrc));
}
__device__ __forceinline__ void cp_commit() { asm volatile("cp.async.commit_group;" ::: "memory"); }
__device__ __forceinline__ void cp_wait_all() { asm volatile("cp.async.wait_all;" ::: "memory"); }
__device__ __forceinline__ uint32_t h2u(__half2 h) { return *(uint32_t*)&h; }

// -------- SMEM layout (dynamic), double-buffered --------
#define SM_B1   0
#define SM_W2   256
#define SM_PART 512
#define SM_AH0  1536
#define SM_AH1  (SM_AH0 + MT * STRA)      // +22528 = 24064
#define SM_BH0  (SM_AH1 + MT * STRA)      // 46592
#define SM_BH1  (SM_BH0 + 80 * STRB)      // +11520 = 58112
#define SMEMSZ  (SM_BH1 + 80 * STRB)      // 69632 bytes -> 3 CTAs/SM

// ---- setup split so mlp stays launch #4 (ncu captures #4) ----
__global__ void clear_sum_a() {
    int i = blockIdx.x * blockDim.x + threadIdx.x;
    if (i < GMAXN / 2) g_sum[i] = 0.0f;
}
__global__ void clear_sum_b() {
    int i = blockIdx.x * blockDim.x + threadIdx.x;
    if (i < GMAXN / 2) g_sum[GMAXN / 2 + i] = 0.0f;
}
__global__ void w1cvt_kernel(const float* __restrict__ W1) {
    int i = blockIdx.x * blockDim.x + threadIdx.x;
    if (i < KW1 * HID_) g_w1h[i] = __float2half(W1[i]);
}

__global__ __launch_bounds__(256, 3) void mlp_mma_kernel(
    const float* __restrict__ src, const float* __restrict__ dst,
    const float* __restrict__ attr, const float* __restrict__ b1,
    const float* __restrict__ W2, const float* __restrict__ b2,
    const int* __restrict__ gidx, float* __restrict__ out,
    int E, long long out_size)
{
    extern __shared__ char smem[];
    const uint32_t sbase = smem_u32(smem);
    const int tid = threadIdx.x;
    const int wid = tid >> 5;
    const int lane = tid & 31;
    const int tile = blockIdx.x >> 1;
    const int nhalf = blockIdx.x & 1;     // which 64 of HID this CTA owns
    const int e0 = tile * MT;

    float* b1s  = (float*)(smem + SM_B1);   // 64 entries (this CTA's cols)
    float* w2s  = (float*)(smem + SM_W2);
    float* part = (float*)(smem + SM_PART); // 128 per-row partial logits
    if (tid < 64) { b1s[tid] = b1[nhalf * 64 + tid]; w2s[tid] = W2[nhalf * 64 + tid]; }
    if (tid < MT) part[tid] = 0.0f;

    const int m_warp = (wid >> 1) * 32;   // 0,32,64,96
    const int n_warp = (wid & 1) * 32;    // 0,32  (local col)

    // loader roles
    const int arow = tid >> 1;            // 0..127
    const int ahalf = tid & 1;            // 32-col half of the 64-col A panel
    const int e = e0 + arow;
    const bool valid = (e < E);
    const int brow = tid >> 2;            // 0..63 (k-row within panel)
    const int bq = tid & 3;               // 32B quarter of 128B B row
    const uint32_t abyte = (uint32_t)arow * STRA + (uint32_t)ahalf * 64u;
    const uint32_t bbyte = (uint32_t)brow * STRB + (uint32_t)bq * 32u;

    float acc[2][4][4];                   // warp tile 32x32
    #pragma unroll
    for (int mb = 0; mb < 2; mb++)
        #pragma unroll
        for (int nt = 0; nt < 4; nt++)
            #pragma unroll
            for (int c = 0; c < 4; c++) acc[mb][nt][c] = 0.0f;

    const uint32_t a_lrow = (uint32_t)(lane & 15);
    const uint32_t a_lcol = (uint32_t)(lane >> 4) * 16u;

    __half2 apf[16];
    __half2 apf2[4];

    // ---- prologue: prefetch panel 0 ----
    {
        if (valid) {
            const float* bp = src + (size_t)e * D_ + ahalf * 32;
            #pragma unroll
            for (int q = 0; q < 8; q++) {
                float4 f = ((const float4*)bp)[q];
                apf[2 * q]     = __floats2half2_rn(f.x, f.y);
                apf[2 * q + 1] = __floats2half2_rn(f.z, f.w);
            }
        } else {
            #pragma unroll
            for (int j = 0; j < 16; j++) apf[j] = __floats2half2_rn(0.f, 0.f);
        }
        const __half* gs = g_w1h + (size_t)brow * HID_ + nhalf * 64 + bq * 16;
        const uint32_t bd = sbase + SM_BH0 + bbyte;
        cp16(bd, gs); cp16(bd + 16, gs + 8);
        cp_commit();
    }

    #pragma unroll 1
    for (int p = 0; p < 4; p++) {
        const uint32_t sm_a = (p & 1) ? SM_AH1 : SM_AH0;
        const uint32_t sm_b = (p & 1) ? SM_BH1 : SM_BH0;

        #pragma unroll
        for (int q = 0; q < 4; q++)
            *(uint4*)(smem + sm_a + abyte + q * 16) =
                make_uint4(h2u(apf[4 * q]), h2u(apf[4 * q + 1]),
                           h2u(apf[4 * q + 2]), h2u(apf[4 * q + 3]));
        if (p == 3)
            *(uint4*)(smem + sm_a + (uint32_t)arow * STRA + 128u + (uint32_t)ahalf * 16u) =
                make_uint4(h2u(apf2[0]), h2u(apf2[1]), h2u(apf2[2]), h2u(apf2[3]));

        cp_wait_all();
        __syncthreads();

        // ---- prefetch next panel (overlapped with MMAs) ----
        if (p < 3) {
            const int pn = p + 1;
            if (valid) {
                const float* bp = ((pn == 1) ? src + 64 : (pn == 2) ? dst : dst + 64)
                                + (size_t)e * D_ + ahalf * 32;
                #pragma unroll
                for (int q = 0; q < 8; q++) {
                    float4 f = ((const float4*)bp)[q];
                    apf[2 * q]     = __floats2half2_rn(f.x, f.y);
                    apf[2 * q + 1] = __floats2half2_rn(f.z, f.w);
                }
            } else {
                #pragma unroll
                for (int j = 0; j < 16; j++) apf[j] = __floats2half2_rn(0.f, 0.f);
            }
            if (pn == 3) {
                if (valid) {
                    const float* ap = attr + (size_t)e * A_ + ahalf * 8;
                    float4 f0 = ((const float4*)ap)[0];
                    float4 f1 = ((const float4*)ap)[1];
                    apf2[0] = __floats2half2_rn(f0.x, f0.y);
                    apf2[1] = __floats2half2_rn(f0.z, f0.w);
                    apf2[2] = __floats2half2_rn(f1.x, f1.y);
                    apf2[3] = __floats2half2_rn(f1.z, f1.w);
                } else {
                    #pragma unroll
                    for (int j = 0; j < 4; j++) apf2[j] = __floats2half2_rn(0.f, 0.f);
                }
            }
            {
                const uint32_t nb_buf = (pn & 1) ? SM_BH1 : SM_BH0;
                const __half* gs = g_w1h + (size_t)(pn * 64 + brow) * HID_ + nhalf * 64 + bq * 16;
                const uint32_t bd = sbase + nb_buf + bbyte;
                cp16(bd, gs); cp16(bd + 16, gs + 8);
                if (pn == 3 && tid < 64) {
                    const int rl = 64 + (tid >> 2);   // local rows 64..79 = k 256..271
                    const __half* gs2 = g_w1h + (size_t)(192 + rl) * HID_ + nhalf * 64 + (tid & 3) * 16;
                    const uint32_t bd2 = sbase + nb_buf + (uint32_t)rl * STRB + (uint32_t)(tid & 3) * 32u;
                    cp16(bd2, gs2); cp16(bd2 + 16, gs2 + 8);
                }
                cp_commit();
            }
        }

        // ---- MMAs on current panel ----
        const int kend = (p == 3) ? 5 : 4;
        #pragma unroll 1
        for (int ks = 0; ks < kend; ks++) {
            const uint32_t kcolb = (uint32_t)ks * 32u + a_lcol;
            uint32_t ah[2][4];
            #pragma unroll
            for (int mb = 0; mb < 2; mb++)
                ldsm_x4(ah[mb], sbase + sm_a
                        + (uint32_t)(m_warp + mb * 16 + a_lrow) * STRA + kcolb);
            const uint32_t brow_b = sbase + sm_b + (uint32_t)(ks * 16 + a_lrow) * STRB
                                  + (uint32_t)(n_warp * 2) + a_lcol;
            uint32_t bh[4];
            ldsm_x4_t(bh, brow_b);            // local cols n_warp .. +16
            #pragma unroll
            for (int mb = 0; mb < 2; mb++) {
                mma16816(acc[mb][0], ah[mb], bh[0], bh[1]);
                mma16816(acc[mb][1], ah[mb], bh[2], bh[3]);
            }
            ldsm_x4_t(bh, brow_b + 32u);      // local cols n_warp+16 .. +32
            #pragma unroll
            for (int mb = 0; mb < 2; mb++) {
                mma16816(acc[mb][2], ah[mb], bh[0], bh[1]);
                mma16816(acc[mb][3], ah[mb], bh[2], bh[3]);
            }
        }
    }

    // ---- epilogue: relu(+b1) dot W2 over this CTA's 64 cols ----
    __syncthreads();
    float s[2][2];
    #pragma unroll
    for (int mb = 0; mb < 2; mb++) { s[mb][0] = 0.0f; s[mb][1] = 0.0f; }
    #pragma unroll
    for (int mb = 0; mb < 2; mb++)
        #pragma unroll
        for (int nt = 0; nt < 4; nt++) {
            const int lc = n_warp + nt * 8 + (lane & 3) * 2;   // local col 0..63
            const float w20 = w2s[lc], w21 = w2s[lc + 1];
            const float bb0 = b1s[lc], bb1 = b1s[lc + 1];
            s[mb][0] = fmaf(fmaxf(acc[mb][nt][0] + bb0, 0.0f), w20, s[mb][0]);
            s[mb][0] = fmaf(fmaxf(acc[mb][nt][1] + bb1, 0.0f), w21, s[mb][0]);
            s[mb][1] = fmaf(fmaxf(acc[mb][nt][2] + bb0, 0.0f), w20, s[mb][1]);
            s[mb][1] = fmaf(fmaxf(acc[mb][nt][3] + bb1, 0.0f), w21, s[mb][1]);
        }
    #pragma unroll
    for (int mb = 0; mb < 2; mb++)
        #pragma unroll
        for (int rh = 0; rh < 2; rh++) {
            s[mb][rh] += __shfl_xor_sync(0xffffffffu, s[mb][rh], 1);
            s[mb][rh] += __shfl_xor_sync(0xffffffffu, s[mb][rh], 2);
        }
    if ((lane & 3) == 0) {
        const int rbase = m_warp + (lane >> 2);
        atomicAdd(&part[rbase],      s[0][0]);
        atomicAdd(&part[rbase + 8],  s[0][1]);
        atomicAdd(&part[rbase + 16], s[1][0]);
        atomicAdd(&part[rbase + 24], s[1][1]);
    }
    __syncthreads();

    // ---- cross-CTA join: biased double atomicAdd; 2nd arriver finalizes ----
    if (tid < MT) {
        const int eo = e0 + tid;
        if (eo < E) {
            const double pd = (double)part[tid] + BIAS1;
            const double ret = atomicAdd(&g_partd[eo], pd);
            if (ret != 0.0) {   // I'm the second half: ret = other's biased partial
                const float lg = (float)(ret + pd - BIAS2) + b2[0];
                out[(long long)E + eo] = lg;
                unsigned g = (unsigned)gidx[eo];
                if (g >= GMAXN) g = 0;
                atomicAdd(&g_sum[g], expf(lg));
            }
        }
    }
}

__global__ void final_kernel(const int* __restrict__ gidx, float* __restrict__ out,
                             int E, long long out_size) {
    const int e = blockIdx.x * blockDim.x + threadIdx.x;
    if (e < E) {
        unsigned g = (unsigned)gidx[e];
        if (g >= GMAXN) g = 0;
        const float lg = out[(long long)E + e];
        const float w = expf(lg) / g_sum[g];
        if ((long long)e < out_size) out[e] = w;
        g_partd[e] = 0.0;   // reset for next (graph-replayed) run
    }
}

extern "C" void kernel_launch(void* const* d_in, const int* in_sizes, int n_in,
                              void* d_out, int out_size) {
    const float* src  = (const float*)d_in[0];
    const float* dst  = (const float*)d_in[1];
    const float* attr = (const float*)d_in[2];
    const float* W1   = (const float*)d_in[3];
    const float* b1   = (const float*)d_in[4];
    const float* W2   = (const float*)d_in[5];
    const float* b2   = (const float*)d_in[6];
    const int*   gidx = (const int*)d_in[7];
    const int E = in_sizes[7];

    float* out = (float*)d_out;

    cudaFuncSetAttribute(mlp_mma_kernel, cudaFuncAttributeMaxDynamicSharedMemorySize, SMEMSZ);

    const int ntile = (E + MT - 1) / MT;
    clear_sum_a<<<(GMAXN / 2 + 255) / 256, 256>>>();                  // #1
    clear_sum_b<<<(GMAXN / 2 + 255) / 256, 256>>>();                  // #2
    w1cvt_kernel<<<(KW1 * HID_ + 255) / 256, 256>>>(W1);              // #3
    mlp_mma_kernel<<<2 * ntile, 256, SMEMSZ>>>(src, dst, attr, b1, W2, b2,
                                               gidx, out, E, (long long)out_size);  // #4
    final_kernel<<<(E + 255) / 256, 256>>>(gidx, out, E, (long long)out_size);      // #5
}

// round 15
// speedup vs baseline: 1.7797x; 1.7797x over previous
#include <cuda_runtime.h>
#include <cuda_fp16.h>
#include <math.h>
#include <stdint.h>

#define D_    128
#define A_    16
#define HID_  128
#define KW1   272
#define MT    128
#define EMAX  1000000
#define GMAXN 25600
#define STRA  176      // A smem row stride bytes (80 fp16 = 160B + 16 pad)
#define STRB  272      // B smem row stride bytes (128 fp16 = 256B + 16 pad)

// -------- scratch (device globals; no allocs allowed) --------
__device__ float g_sum[GMAXN];
__device__ __align__(16) __half g_w1h[KW1 * HID_];   // W1 fp16 [k][n]

__device__ __forceinline__ uint32_t smem_u32(const void* p) {
    uint32_t a;
    asm("{ .reg .u64 t; cvta.to.shared.u64 t, %1; cvt.u32.u64 %0, t; }" : "=r"(a) : "l"(p));
    return a;
}
__device__ __forceinline__ void ldsm_x4(uint32_t* r, uint32_t addr) {
    asm volatile("ldmatrix.sync.aligned.m8n8.x4.shared.b16 {%0,%1,%2,%3}, [%4];"
                 : "=r"(r[0]), "=r"(r[1]), "=r"(r[2]), "=r"(r[3]) : "r"(addr));
}
__device__ __forceinline__ void ldsm_x4_t(uint32_t* r, uint32_t addr) {
    asm volatile("ldmatrix.sync.aligned.m8n8.x4.trans.shared.b16 {%0,%1,%2,%3}, [%4];"
                 : "=r"(r[0]), "=r"(r[1]), "=r"(r[2]), "=r"(r[3]) : "r"(addr));
}
__device__ __forceinline__ void mma16816(float* c, const uint32_t* a, uint32_t b0, uint32_t b1) {
    asm volatile("mma.sync.aligned.m16n8k16.row.col.f32.f16.f16.f32 "
                 "{%0,%1,%2,%3}, {%4,%5,%6,%7}, {%8,%9}, {%0,%1,%2,%3};"
                 : "+f"(c[0]), "+f"(c[1]), "+f"(c[2]), "+f"(c[3])
                 : "r"(a[0]), "r"(a[1]), "r"(a[2]), "r"(a[3]), "r"(b0), "r"(b1));
}
__device__ __forceinline__ void cp16(uint32_t sdst, const void* gsrc) {
    asm volatile("cp.async.cg.shared.global [%0], [%1], 16;" :: "r"(sdst), "l"(gsrc));
}
__device__ __forceinline__ void cp_commit() { asm volatile("cp.async.commit_group;" ::: "memory"); }
__device__ __forceinline__ void cp_wait_all() { asm volatile("cp.async.wait_all;" ::: "memory"); }
__device__ __forceinline__ uint32_t h2u(__half2 h) { return *(uint32_t*)&h; }

// -------- SMEM layout (dynamic), double-buffered panels --------
#define SM_B1   0
#define SM_W2   512
#define SM_P0   1024                      // part buffer for n_warp=0 warps
#define SM_P1   1536                      // part buffer for n_warp=64 warps
#define SM_AH0  2048
#define SM_AH1  (SM_AH0 + MT * STRA)      // +22528
#define SM_BH0  (SM_AH1 + MT * STRA)
#define SM_BH1  (SM_BH0 + 80 * STRB)      // +21760
#define SMEMSZ  (SM_BH1 + 80 * STRB)      // 90624 bytes -> 2 CTAs/SM (reg-limited anyway)

// ---- merged setup: clear group sums + convert W1 to fp16 ----
__global__ void setup_kernel(const float* __restrict__ W1) {
    int i = blockIdx.x * blockDim.x + threadIdx.x;
    if (i < GMAXN) g_sum[i] = 0.0f;
    if (i < KW1 * HID_) g_w1h[i] = __float2half(W1[i]);
}

#define KSTEP(ks)                                                                  \
    {                                                                              \
        const uint32_t kcolb = (uint32_t)(ks) * 32u + a_lcol;                      \
        uint32_t ah[2][4];                                                         \
        _Pragma("unroll")                                                          \
        for (int mb = 0; mb < 2; mb++)                                             \
            ldsm_x4(ah[mb], sbase + sm_a                                           \
                    + (uint32_t)(m_warp + mb * 16 + a_lrow) * STRA + kcolb);       \
        _Pragma("unroll")                                                          \
        for (int nb = 0; nb < 4; nb++) {                                           \
            uint32_t bh[4];                                                        \
            ldsm_x4_t(bh, sbase + sm_b                                             \
                      + (uint32_t)((ks) * 16 + a_lrow) * STRB                      \
                      + (uint32_t)(n_warp * 2 + nb * 32) + a_lcol);                \
            _Pragma("unroll")                                                      \
            for (int mb = 0; mb < 2; mb++) {                                       \
                mma16816(acc[mb][2 * nb],     ah[mb], bh[0], bh[1]);               \
                mma16816(acc[mb][2 * nb + 1], ah[mb], bh[2], bh[3]);               \
            }                                                                      \
        }                                                                          \
    }

__global__ __launch_bounds__(256, 2) void mlp_mma_kernel(
    const float* __restrict__ src, const float* __restrict__ dst,
    const float* __restrict__ attr, const float* __restrict__ b1,
    const float* __restrict__ W2, const float* __restrict__ b2,
    const int* __restrict__ gidx, float* __restrict__ out,
    int E, long long out_size)
{
    extern __shared__ char smem[];
    const uint32_t sbase = smem_u32(smem);
    const int tid = threadIdx.x;
    const int wid = tid >> 5;
    const int lane = tid & 31;
    const int e0 = blockIdx.x * MT;

    float* b1s = (float*)(smem + SM_B1);
    float* w2s = (float*)(smem + SM_W2);
    float* p0  = (float*)(smem + SM_P0);
    float* p1  = (float*)(smem + SM_P1);
    if (tid < HID_) { b1s[tid] = b1[tid]; w2s[tid] = W2[tid]; }

    const int m_warp = (wid >> 1) * 32;
    const int n_warp = (wid & 1) * 64;

    const int arow = tid >> 1;
    const int ahalf = tid & 1;
    const int e = e0 + arow;
    const bool valid = (e < E);
    const int brow = tid >> 2;
    const int bq = tid & 3;
    const uint32_t abyte = (uint32_t)arow * STRA + (uint32_t)ahalf * 64u;
    const uint32_t bbyte = (uint32_t)brow * STRB + (uint32_t)bq * 64u;

    float acc[2][8][4];
    #pragma unroll
    for (int mb = 0; mb < 2; mb++)
        #pragma unroll
        for (int nt = 0; nt < 8; nt++)
            #pragma unroll
            for (int c = 0; c < 4; c++) acc[mb][nt][c] = 0.0f;

    const uint32_t a_lrow = (uint32_t)(lane & 15);
    const uint32_t a_lcol = (uint32_t)(lane >> 4) * 16u;

    __half2 apf[16];
    __half2 apf2[4];

    // ---- prologue: prefetch panel 0 ----
    {
        if (valid) {
            const float* bp = src + (size_t)e * D_ + ahalf * 32;
            #pragma unroll
            for (int q = 0; q < 8; q++) {
                float4 f = ((const float4*)bp)[q];
                apf[2 * q]     = __floats2half2_rn(f.x, f.y);
                apf[2 * q + 1] = __floats2half2_rn(f.z, f.w);
            }
        } else {
            #pragma unroll
            for (int j = 0; j < 16; j++) apf[j] = __floats2half2_rn(0.f, 0.f);
        }
        const __half* gs = g_w1h + (size_t)brow * HID_ + bq * 32;
        const uint32_t bd = sbase + SM_BH0 + bbyte;
        #pragma unroll
        for (int q = 0; q < 4; q++) cp16(bd + q * 16, gs + q * 8);
        cp_commit();
    }

    for (int p = 0; p < 4; p++) {
        const uint32_t sm_a = (p & 1) ? SM_AH1 : SM_AH0;
        const uint32_t sm_b = (p & 1) ? SM_BH1 : SM_BH0;

        #pragma unroll
        for (int q = 0; q < 4; q++)
            *(uint4*)(smem + sm_a + abyte + q * 16) =
                make_uint4(h2u(apf[4 * q]), h2u(apf[4 * q + 1]),
                           h2u(apf[4 * q + 2]), h2u(apf[4 * q + 3]));
        if (p == 3)
            *(uint4*)(smem + sm_a + (uint32_t)arow * STRA + 128u + (uint32_t)ahalf * 16u) =
                make_uint4(h2u(apf2[0]), h2u(apf2[1]), h2u(apf2[2]), h2u(apf2[3]));

        cp_wait_all();
        __syncthreads();

        // ---- prefetch next panel (overlapped with MMAs) ----
        if (p < 3) {
            const int pn = p + 1;
            if (valid) {
                const float* bp = ((pn == 1) ? src + 64 : (pn == 2) ? dst : dst + 64)
                                + (size_t)e * D_ + ahalf * 32;
                #pragma unroll
                for (int q = 0; q < 8; q++) {
                    float4 f = ((const float4*)bp)[q];
                    apf[2 * q]     = __floats2half2_rn(f.x, f.y);
                    apf[2 * q + 1] = __floats2half2_rn(f.z, f.w);
                }
            } else {
                #pragma unroll
                for (int j = 0; j < 16; j++) apf[j] = __floats2half2_rn(0.f, 0.f);
            }
            if (pn == 3) {
                if (valid) {
                    const float* ap = attr + (size_t)e * A_ + ahalf * 8;
                    float4 f0 = ((const float4*)ap)[0];
                    float4 f1 = ((const float4*)ap)[1];
                    apf2[0] = __floats2half2_rn(f0.x, f0.y);
                    apf2[1] = __floats2half2_rn(f0.z, f0.w);
                    apf2[2] = __floats2half2_rn(f1.x, f1.y);
                    apf2[3] = __floats2half2_rn(f1.z, f1.w);
                } else {
                    #pragma unroll
                    for (int j = 0; j < 4; j++) apf2[j] = __floats2half2_rn(0.f, 0.f);
                }
            }
            {
                const uint32_t nb_buf = (pn & 1) ? SM_BH1 : SM_BH0;
                const __half* gs = g_w1h + (size_t)(pn * 64 + brow) * HID_ + bq * 32;
                const uint32_t bd = sbase + nb_buf + bbyte;
                #pragma unroll
                for (int q = 0; q < 4; q++) cp16(bd + q * 16, gs + q * 8);
                if (pn == 3 && tid < 64) {
                    const int rl = 64 + (tid >> 2);
                    const __half* gs2 = g_w1h + (size_t)(192 + rl) * HID_ + (tid & 3) * 32;
                    const uint32_t bd2 = sbase + nb_buf + (uint32_t)rl * STRB + (uint32_t)(tid & 3) * 64u;
                    #pragma unroll
                    for (int q = 0; q < 4; q++) cp16(bd2 + q * 16, gs2 + q * 8);
                }
                cp_commit();
            }
        }

        // ---- MMAs on current panel ----
        if (p < 3) {
            #pragma unroll
            for (int ks = 0; ks < 4; ks++) KSTEP(ks)
        } else {
            #pragma unroll
            for (int ks = 0; ks < 5; ks++) KSTEP(ks)
        }
    }

    // ---- epilogue: relu(+b1) dot W2 -> per-row partials (no atomics) ----
    __syncthreads();
    float s[2][2];
    #pragma unroll
    for (int mb = 0; mb < 2; mb++) { s[mb][0] = 0.0f; s[mb][1] = 0.0f; }
    #pragma unroll
    for (int mb = 0; mb < 2; mb++)
        #pragma unroll
        for (int nt = 0; nt < 8; nt++) {
            const int c0 = n_warp + nt * 8 + (lane & 3) * 2;
            const float w20 = w2s[c0], w21 = w2s[c0 + 1];
            const float bb0 = b1s[c0], bb1 = b1s[c0 + 1];
            s[mb][0] = fmaf(fmaxf(acc[mb][nt][0] + bb0, 0.0f), w20, s[mb][0]);
            s[mb][0] = fmaf(fmaxf(acc[mb][nt][1] + bb1, 0.0f), w21, s[mb][0]);
            s[mb][1] = fmaf(fmaxf(acc[mb][nt][2] + bb0, 0.0f), w20, s[mb][1]);
            s[mb][1] = fmaf(fmaxf(acc[mb][nt][3] + bb1, 0.0f), w21, s[mb][1]);
        }
    #pragma unroll
    for (int mb = 0; mb < 2; mb++)
        #pragma unroll
        for (int rh = 0; rh < 2; rh++) {
            s[mb][rh] += __shfl_xor_sync(0xffffffffu, s[mb][rh], 1);
            s[mb][rh] += __shfl_xor_sync(0xffffffffu, s[mb][rh], 2);
        }
    if ((lane & 3) == 0) {
        float* pw = (wid & 1) ? p1 : p0;   // disjoint writer sets per buffer
        const int rbase = m_warp + (lane >> 2);
        pw[rbase]      = s[0][0];
        pw[rbase + 8]  = s[0][1];
        pw[rbase + 16] = s[1][0];
        pw[rbase + 24] = s[1][1];
    }
    __syncthreads();

    if (tid < MT) {
        const int eo = e0 + tid;
        if (eo < E) {
            const float lg = p0[tid] + p1[tid] + b2[0];
            out[(long long)E + eo] = lg;              // logits half of output
            unsigned g = (unsigned)gidx[eo];
            if (g >= GMAXN) g = 0;
            atomicAdd(&g_sum[g], expf(lg));           // unshifted softmax sum
        }
    }
}

__global__ void final_kernel(const int* __restrict__ gidx, float* __restrict__ out,
                             int E, long long out_size) {
    const int i = (blockIdx.x * blockDim.x + threadIdx.x) * 4;
    if (i + 3 < E) {
        const int4   g4 = *(const int4*)(gidx + i);
        const float4 l4 = *(const float4*)(out + (size_t)E + i);
        const unsigned ga = ((unsigned)g4.x < GMAXN) ? (unsigned)g4.x : 0u;
        const unsigned gb = ((unsigned)g4.y < GMAXN) ? (unsigned)g4.y : 0u;
        const unsigned gc = ((unsigned)g4.z < GMAXN) ? (unsigned)g4.z : 0u;
        const unsigned gd = ((unsigned)g4.w < GMAXN) ? (unsigned)g4.w : 0u;
        float4 w;
        w.x = expf(l4.x) / g_sum[ga];
        w.y = expf(l4.y) / g_sum[gb];
        w.z = expf(l4.z) / g_sum[gc];
        w.w = expf(l4.w) / g_sum[gd];
        *(float4*)(out + i) = w;
    } else {
        for (int e = i; e < E; e++) {
            unsigned g = (unsigned)gidx[e];
            if (g >= GMAXN) g = 0;
            out[e] = expf(out[(size_t)E + e]) / g_sum[g];
        }
    }
}

extern "C" void kernel_launch(void* const* d_in, const int* in_sizes, int n_in,
                              void* d_out, int out_size) {
    const float* src  = (const float*)d_in[0];
    const float* dst  = (const float*)d_in[1];
    const float* attr = (const float*)d_in[2];
    const float* W1   = (const float*)d_in[3];
    const float* b1   = (const float*)d_in[4];
    const float* W2   = (const float*)d_in[5];
    const float* b2   = (const float*)d_in[6];
    const int*   gidx = (const int*)d_in[7];
    const int E = in_sizes[7];

    float* out = (float*)d_out;

    cudaFuncSetAttribute(mlp_mma_kernel, cudaFuncAttributeMaxDynamicSharedMemorySize, SMEMSZ);

    const int setup_n = (KW1 * HID_ > GMAXN) ? KW1 * HID_ : GMAXN;
    setup_kernel<<<(setup_n + 255) / 256, 256>>>(W1);
    mlp_mma_kernel<<<(E + MT - 1) / MT, 256, SMEMSZ>>>(src, dst, attr, b1, W2, b2,
                                                       gidx, out, E, (long long)out_size);
    final_kernel<<<(E / 4 + 255) / 256, 256>>>(gidx, out, E, (long long)out_size);
}